// round 2
// baseline (speedup 1.0000x reference)
#include <cuda_runtime.h>
#include <math.h>

// ---------------- problem constants ----------------
// B=64, T=2048, N=131072 tokens, C_IN=44, D=512, DC=640, RED=160
#define NTOK   131072
#define TSEQ_SHIFT 11          // T = 2048 = 1<<11
#define DCOMB  640
#define DOUT   512

// ---------------- scratch (device globals; no allocation allowed) ----------------
__device__ float g_a1 [(long long)NTOK * 640];   // stage-1 activations; reused as h after LN
__device__ float g_z  [(long long)NTOK * 640];   // concat(z_h, z_l, z_e)
__device__ float g_y  [(long long)NTOK * 1280];  // [gate-preact | p-preact]
__device__ float g_o  [(long long)NTOK * 512];   // pre-GroupNorm output
__device__ float g_zsum[64 * 640];
__device__ float g_se  [64 * 640];
__device__ float g_gn  [64 * 8 * 2];             // (mean, rstd) per (batch, group)

// ---------------- helpers ----------------
__device__ __forceinline__ float2 ffma2(float2 a, float2 b, float2 c) {
    float2 d;
    asm("fma.rn.f32x2 %0, %1, %2, %3;"
        : "=l"(*(unsigned long long*)&d)
        : "l"(*(unsigned long long*)&a),
          "l"(*(unsigned long long*)&b),
          "l"(*(unsigned long long*)&c));
    return d;
}

__device__ __forceinline__ float warp_sum(float v) {
    #pragma unroll
    for (int o = 16; o > 0; o >>= 1) v += __shfl_down_sync(0xffffffffu, v, o);
    return v;
}

__device__ __forceinline__ float sigmoid_f(float x) { return 1.f / (1.f + __expf(-x)); }

// ---------------- tiled SGEMM: C[M,N] = act(A[M,K] @ W[K,N] + bias) ----------------
// BM=BN=128, BK=16, 256 threads, 8x8 microtile via packed f32x2 FMA.
// M (=131072) and N are multiples of 128 for every call; K may be ragged (zero-padded).
// Optional per-row A scale: a *= se[(row>>11)*640 + k]  (fuses z_se = z * se[batch]).
#define BM 128
#define BN 128
#define BK 16

__global__ __launch_bounds__(256, 2)
void sgemm(const float* __restrict__ A, int lda,
           const float* __restrict__ W, int ldw,
           const float* __restrict__ bias,
           float* __restrict__ C, int ldc,
           int K, int act, const float* __restrict__ se)
{
    __shared__ float As[BK][BM + 1];
    __shared__ float Bs[BK][BN];

    const int tid = threadIdx.x;
    const int tx = tid & 15;     // 0..15 -> column groups
    const int ty = tid >> 4;     // 0..15 -> row groups
    const long long rowTile = (long long)blockIdx.y * BM;
    const int colTile = blockIdx.x * BN;

    float2 acc[8][4];
    #pragma unroll
    for (int i = 0; i < 8; i++)
        #pragma unroll
        for (int j = 0; j < 4; j++) acc[i][j] = make_float2(0.f, 0.f);

    for (int k0 = 0; k0 < K; k0 += BK) {
        // load A tile (2048 elems, 8/thread), coalesced over k, store transposed
        #pragma unroll
        for (int i = 0; i < 8; i++) {
            int idx = tid + i * 256;
            int m = idx >> 4, kk = idx & 15;
            int kg = k0 + kk;
            long long row = rowTile + m;
            float v = 0.f;
            if (kg < K) {
                v = A[row * lda + kg];
                if (se) v *= se[(int)(row >> TSEQ_SHIFT) * 640 + kg];
            }
            As[kk][m] = v;
        }
        // load B tile (2048 elems, 8/thread), coalesced over n
        #pragma unroll
        for (int i = 0; i < 8; i++) {
            int idx = tid + i * 256;
            int kk = idx >> 7, n = idx & 127;
            int kg = k0 + kk;
            Bs[kk][n] = (kg < K) ? W[(long long)kg * ldw + colTile + n] : 0.f;
        }
        __syncthreads();

        #pragma unroll
        for (int kk = 0; kk < BK; kk++) {
            float2 b[4];
            float a[8];
            #pragma unroll
            for (int j = 0; j < 4; j++)
                b[j] = *(const float2*)&Bs[kk][tx * 2 + j * 32];
            #pragma unroll
            for (int i = 0; i < 8; i++)
                a[i] = As[kk][ty * 8 + i];
            #pragma unroll
            for (int i = 0; i < 8; i++) {
                float2 a2 = make_float2(a[i], a[i]);
                #pragma unroll
                for (int j = 0; j < 4; j++)
                    acc[i][j] = ffma2(a2, b[j], acc[i][j]);
            }
        }
        __syncthreads();
    }

    // epilogue: bias (+ optional SiLU), float2 stores
    #pragma unroll
    for (int i = 0; i < 8; i++) {
        long long row = rowTile + ty * 8 + i;
        #pragma unroll
        for (int j = 0; j < 4; j++) {
            int col = colTile + tx * 2 + j * 32;
            float2 v = acc[i][j];
            v.x += bias[col];
            v.y += bias[col + 1];
            if (act == 1) {
                v.x = v.x * sigmoid_f(v.x);
                v.y = v.y * sigmoid_f(v.y);
            }
            *(float2*)&C[row * ldc + col] = v;
        }
    }
}

// ---------------- per-batch column sum of z over T (for SE pooling) ----------------
__global__ __launch_bounds__(128)
void zsum_kernel(const float* __restrict__ z, float* __restrict__ zsum)
{
    int b = blockIdx.y;
    int c = blockIdx.x * 128 + threadIdx.x;
    const float* base = z + (long long)b * 2048 * 640 + c;
    float s0 = 0.f, s1 = 0.f, s2 = 0.f, s3 = 0.f;
    for (int t = 0; t < 2048; t += 4) {
        s0 += base[(long long)(t    ) * 640];
        s1 += base[(long long)(t + 1) * 640];
        s2 += base[(long long)(t + 2) * 640];
        s3 += base[(long long)(t + 3) * 640];
    }
    zsum[b * 640 + c] = (s0 + s1) + (s2 + s3);
}

// ---------------- SE block: se = sigmoid(relu(avg @ w1) @ w2) ----------------
__global__ __launch_bounds__(256)
void se_kernel(const float* __restrict__ zsum, const float* __restrict__ w1,
               const float* __restrict__ w2, float* __restrict__ se)
{
    int b = blockIdx.x;
    __shared__ float avg[640];
    __shared__ float r[160];
    for (int c = threadIdx.x; c < 640; c += 256)
        avg[c] = zsum[b * 640 + c] * (1.f / 2048.f);
    __syncthreads();
    for (int j = threadIdx.x; j < 160; j += 256) {
        float s = 0.f;
        for (int k = 0; k < 640; k++) s += avg[k] * w1[k * 160 + j];
        r[j] = fmaxf(s, 0.f);
    }
    __syncthreads();
    for (int j = threadIdx.x; j < 640; j += 256) {
        float s = 0.f;
        for (int k = 0; k < 160; k++) s += r[k] * w2[k * 640 + j];
        se[b * 640 + j] = sigmoid_f(s);
    }
}

// ---------------- gate + LayerNorm (one block per token, 320 threads) ----------------
__global__ __launch_bounds__(320)
void gate_ln_kernel(const float* __restrict__ z, const float* __restrict__ se,
                    const float* __restrict__ y,
                    const float* __restrict__ lnw, const float* __restrict__ lnb,
                    float* __restrict__ hout)
{
    long long row = blockIdx.x;
    const float* zr  = z  + row * 640;
    const float* yr  = y  + row * 1280;
    const float* ser = se + (int)(row >> TSEQ_SHIFT) * 640;

    __shared__ float hs[640];
    __shared__ float wsum[10], wsum2[10], stats[2];

    float s = 0.f, s2 = 0.f;
    #pragma unroll
    for (int u = 0; u < 2; u++) {
        int c = threadIdx.x + u * 320;
        float zse = zr[c] * ser[c];
        float gv = sigmoid_f(yr[c]);        // gb already added by GEMM
        float pv = yr[640 + c];             // pb already added by GEMM
        float h = gv * pv + (1.f - gv) * zse;
        hs[c] = h;
        s += h;
        s2 += h * h;
    }
    s  = warp_sum(s);
    s2 = warp_sum(s2);
    int lane = threadIdx.x & 31, wid = threadIdx.x >> 5;
    if (lane == 0) { wsum[wid] = s; wsum2[wid] = s2; }
    __syncthreads();
    if (threadIdx.x == 0) {
        float a = 0.f, b2 = 0.f;
        #pragma unroll
        for (int i = 0; i < 10; i++) { a += wsum[i]; b2 += wsum2[i]; }
        float mu  = a * (1.f / 640.f);
        float var = b2 * (1.f / 640.f) - mu * mu;
        stats[0] = mu;
        stats[1] = rsqrtf(var + 1e-5f);
    }
    __syncthreads();
    float mu = stats[0], rs = stats[1];
    #pragma unroll
    for (int u = 0; u < 2; u++) {
        int c = threadIdx.x + u * 320;
        hout[row * 640 + c] = (hs[c] - mu) * rs * lnw[c] + lnb[c];
    }
}

// ---------------- GroupNorm stats per (batch, group): reduce T x 64 channels ----------------
__global__ __launch_bounds__(256)
void gnstat_kernel(const float* __restrict__ out, float* __restrict__ gst)
{
    int b = blockIdx.y, g = blockIdx.x;
    const float* base = out + (long long)b * 2048 * 512 + g * 64;
    float s = 0.f, s2 = 0.f;
    for (int idx = threadIdx.x; idx < 2048 * 64; idx += 256) {
        int t = idx >> 6, c = idx & 63;
        float v = base[(long long)t * 512 + c];
        s += v;
        s2 += v * v;
    }
    s  = warp_sum(s);
    s2 = warp_sum(s2);
    __shared__ float a[8], a2[8];
    int lane = threadIdx.x & 31, wid = threadIdx.x >> 5;
    if (lane == 0) { a[wid] = s; a2[wid] = s2; }
    __syncthreads();
    if (threadIdx.x == 0) {
        float S = 0.f, S2 = 0.f;
        #pragma unroll
        for (int i = 0; i < 8; i++) { S += a[i]; S2 += a2[i]; }
        double mean = (double)S / 131072.0;
        double var  = (double)S2 / 131072.0 - mean * mean;
        gst[(b * 8 + g) * 2 + 0] = (float)mean;
        gst[(b * 8 + g) * 2 + 1] = (float)rsqrt(var + 1e-5);
    }
}

// ---------------- GroupNorm apply (vectorized) ----------------
__global__ __launch_bounds__(256)
void gnapply_kernel(const float* __restrict__ out, const float* __restrict__ gst,
                    const float* __restrict__ gw, const float* __restrict__ gb,
                    float* __restrict__ dst)
{
    const long long total = (long long)NTOK * 128;  // float4 count per row = 512/4
    for (long long i = (long long)blockIdx.x * blockDim.x + threadIdx.x;
         i < total; i += (long long)gridDim.x * blockDim.x) {
        long long row = i >> 7;
        int q = (int)(i & 127);
        int d = q * 4;
        int b = (int)(row >> TSEQ_SHIFT);
        int g = d >> 6;
        float mean = gst[(b * 8 + g) * 2 + 0];
        float rs   = gst[(b * 8 + g) * 2 + 1];
        float4 v  = *(const float4*)&out[(row << 9) + d];
        float4 w  = *(const float4*)&gw[d];
        float4 bb = *(const float4*)&gb[d];
        float4 r;
        r.x = (v.x - mean) * rs * w.x + bb.x;
        r.y = (v.y - mean) * rs * w.y + bb.y;
        r.z = (v.z - mean) * rs * w.z + bb.z;
        r.w = (v.w - mean) * rs * w.w + bb.w;
        *(float4*)&dst[(row << 9) + d] = r;
    }
}

// ---------------- launch ----------------
extern "C" void kernel_launch(void* const* d_in, const int* in_sizes, int n_in,
                              void* d_out, int out_size)
{
    const float* x    = (const float*)d_in[0];
    const float* hw1  = (const float*)d_in[1];
    const float* hb1  = (const float*)d_in[2];
    const float* hw2  = (const float*)d_in[3];
    const float* hb2  = (const float*)d_in[4];
    const float* lw1  = (const float*)d_in[5];
    const float* lb1  = (const float*)d_in[6];
    const float* lw2  = (const float*)d_in[7];
    const float* lb2  = (const float*)d_in[8];
    const float* ew1  = (const float*)d_in[9];
    const float* eb1  = (const float*)d_in[10];
    const float* eb2w = (const float*)d_in[11];  // ew2
    const float* eb2  = (const float*)d_in[12];
    const float* sew1 = (const float*)d_in[13];
    const float* sew2 = (const float*)d_in[14];
    const float* gwv  = (const float*)d_in[15];
    const float* gbv  = (const float*)d_in[16];
    const float* pwv  = (const float*)d_in[17];
    const float* pbv  = (const float*)d_in[18];
    const float* lnw  = (const float*)d_in[19];
    const float* lnb  = (const float*)d_in[20];
    const float* owv  = (const float*)d_in[21];
    const float* obv  = (const float*)d_in[22];
    const float* gnw  = (const float*)d_in[23];
    const float* gnb  = (const float*)d_in[24];
    float* dst = (float*)d_out;

    float *a1, *z, *y, *ob, *zs, *se, *gn;
    cudaGetSymbolAddress((void**)&a1, g_a1);
    cudaGetSymbolAddress((void**)&z,  g_z);
    cudaGetSymbolAddress((void**)&y,  g_y);
    cudaGetSymbolAddress((void**)&ob, g_o);
    cudaGetSymbolAddress((void**)&zs, g_zsum);
    cudaGetSymbolAddress((void**)&se, g_se);
    cudaGetSymbolAddress((void**)&gn, g_gn);

    const dim3 blk(256);
    const int MY = NTOK / BM;  // 1024

    // stage 1: a1 = silu(x_slice @ w1 + b1)   (cols 0-255: h, 256-511: l, 512-639: e)
    sgemm<<<dim3(2, MY), blk>>>(x +  0, 44, hw1, 256, hb1, a1 +   0, 640, 14, 1, nullptr);
    sgemm<<<dim3(2, MY), blk>>>(x + 14, 44, lw1, 256, lb1, a1 + 256, 640, 22, 1, nullptr);
    sgemm<<<dim3(1, MY), blk>>>(x + 36, 44, ew1, 128, eb1, a1 + 512, 640,  8, 1, nullptr);

    // stage 2: z = a1_branch @ w2 + b2 (block-diagonal)
    sgemm<<<dim3(2, MY), blk>>>(a1 +   0, 640, hw2, 256, hb2, z +   0, 640, 256, 0, nullptr);
    sgemm<<<dim3(2, MY), blk>>>(a1 + 256, 640, lw2, 256, lb2, z + 256, 640, 256, 0, nullptr);
    sgemm<<<dim3(1, MY), blk>>>(a1 + 512, 640, eb2w, 128, eb2, z + 512, 640, 128, 0, nullptr);

    // SE path
    zsum_kernel<<<dim3(5, 64), 128>>>(z, zs);
    se_kernel<<<64, 256>>>(zs, sew1, sew2, se);

    // stage 3: y = (z*se[b]) @ [gw | pw]  (+gb, +pb), A-scale fused in GEMM
    sgemm<<<dim3(5, MY), blk>>>(z, 640, gwv, 640, gbv, y +   0, 1280, 640, 0, se);
    sgemm<<<dim3(5, MY), blk>>>(z, 640, pwv, 640, pbv, y + 640, 1280, 640, 0, se);

    // gate + LayerNorm -> h (reuse a1 buffer)
    gate_ln_kernel<<<NTOK, 320>>>(z, se, y, lnw, lnb, a1);

    // output projection
    sgemm<<<dim3(4, MY), blk>>>(a1, 640, owv, 512, obv, ob, 512, 640, 0, nullptr);

    // GroupNorm(8)
    gnstat_kernel<<<dim3(8, 64), 256>>>(ob, gn);
    gnapply_kernel<<<2048, 256>>>(ob, gn, gnw, gnb, dst);
}

// round 5
// speedup vs baseline: 2.1143x; 2.1143x over previous
#include <cuda_runtime.h>
#include <cstdint>
#include <math.h>

// ---------------- problem constants ----------------
#define NTOK   131072
#define TSEQ_SHIFT 11          // T = 2048
#define DCOMB  640
#define DOUT   512

// ---------------- scratch ----------------
__device__ float g_a1 [(long long)NTOK * 640];
__device__ float g_z  [(long long)NTOK * 640];
__device__ float g_y  [(long long)NTOK * 1280];
__device__ float g_o  [(long long)NTOK * 512];
__device__ float g_zsum[64 * 640];
__device__ float g_se  [64 * 640];
__device__ float g_gn  [64 * 8 * 2];
// transposed weights [N][K] + concatenated bias
__device__ float g_wty[1280 * 640];
__device__ float g_wto[512 * 640];
__device__ float g_wth[256 * 256];
__device__ float g_wtl[256 * 256];
__device__ float g_wte[128 * 128];
__device__ float g_by [1280];

// ---------------- helpers ----------------
__device__ __forceinline__ uint32_t f2tf32(float f) {
    uint32_t r;
    asm("cvt.rna.tf32.f32 %0, %1;" : "=r"(r) : "f"(f));
    return r;
}
__device__ __forceinline__ float tf32f(float f) { return __uint_as_float(f2tf32(f)); }

__device__ __forceinline__ void mma_tf32(float* c, const uint32_t* a, const uint32_t* b) {
    asm volatile(
        "mma.sync.aligned.m16n8k8.row.col.f32.tf32.tf32.f32 "
        "{%0,%1,%2,%3}, {%4,%5,%6,%7}, {%8,%9}, {%0,%1,%2,%3};"
        : "+f"(c[0]), "+f"(c[1]), "+f"(c[2]), "+f"(c[3])
        : "r"(a[0]), "r"(a[1]), "r"(a[2]), "r"(a[3]), "r"(b[0]), "r"(b[1]));
}

__device__ __forceinline__ float warp_sum(float v) {
    #pragma unroll
    for (int o = 16; o > 0; o >>= 1) v += __shfl_down_sync(0xffffffffu, v, o);
    return v;
}
__device__ __forceinline__ float sigmoid_f(float x) { return 1.f / (1.f + __expf(-x)); }

// ---------------- tensor-core tf32 GEMM (mma.sync, sm_80+ PTX) ----------------
// C[M,N] = A[M,K] @ Wt^T + bias ; Wt is [N][K] row-major (pre-transposed W).
// Block: 128(M) x 128(N) x BK=32, 256 threads = 8 warps, warp tile 32(M) x 64(N).
// Optional fused A scale: a *= se[batch(row)*640 + k].
#define TKS 36   // padded smem row stride (floats)

__global__ __launch_bounds__(256, 2)
void mma_gemm(const float* __restrict__ A, int lda,
              const float* __restrict__ Wt,
              const float* __restrict__ bias,
              float* __restrict__ C, int ldc,
              int K, const float* __restrict__ se)
{
    __shared__ float As[128 * TKS];
    __shared__ float Bs[128 * TKS];

    const int tid  = threadIdx.x;
    const int wid  = tid >> 5;
    const int lane = tid & 31;
    const int g    = lane >> 2;     // group row
    const int tig  = lane & 3;      // thread-in-group
    const int warp_m = (wid & 3) * 32;
    const int warp_n = (wid >> 2) * 64;

    const long long rowTile = (long long)blockIdx.y * 128;
    const int colTile = blockIdx.x * 128;
    const float* seRow = se ? (se + (int)(rowTile >> TSEQ_SHIFT) * 640) : nullptr;

    // gmem load assignment: 2 threads per row, 4 float4 each (32 floats/row)
    const int ldRow = tid >> 1;           // 0..127
    const int ldQ   = (tid & 1) * 4;      // float4 index base

    float acc[2][8][4];
    #pragma unroll
    for (int mt = 0; mt < 2; mt++)
        #pragma unroll
        for (int nt = 0; nt < 8; nt++)
            #pragma unroll
            for (int i = 0; i < 4; i++) acc[mt][nt][i] = 0.f;

    for (int k0 = 0; k0 < K; k0 += 32) {
        // load A/B tiles to registers
        float4 va[4], vb[4];
        const float* Ar = A + (rowTile + ldRow) * lda + k0;
        const float* Br = Wt + (long long)(colTile + ldRow) * K + k0;
        #pragma unroll
        for (int i = 0; i < 4; i++) {
            va[i] = *(const float4*)(Ar + (ldQ + i) * 4);
            vb[i] = *(const float4*)(Br + (ldQ + i) * 4);
        }
        if (seRow) {
            #pragma unroll
            for (int i = 0; i < 4; i++) {
                float4 s4 = *(const float4*)(seRow + k0 + (ldQ + i) * 4);
                va[i].x *= s4.x; va[i].y *= s4.y; va[i].z *= s4.z; va[i].w *= s4.w;
            }
        }
        __syncthreads();
        #pragma unroll
        for (int i = 0; i < 4; i++) {
            float* da = &As[ldRow * TKS + (ldQ + i) * 4];
            da[0] = tf32f(va[i].x); da[1] = tf32f(va[i].y);
            da[2] = tf32f(va[i].z); da[3] = tf32f(va[i].w);
            float* db = &Bs[ldRow * TKS + (ldQ + i) * 4];
            db[0] = tf32f(vb[i].x); db[1] = tf32f(vb[i].y);
            db[2] = tf32f(vb[i].z); db[3] = tf32f(vb[i].w);
        }
        __syncthreads();

        const float* Aw = &As[warp_m * TKS];
        const float* Bw = &Bs[warp_n * TKS];
        #pragma unroll
        for (int ks = 0; ks < 4; ks++) {
            const int kk = ks * 8;
            uint32_t af[2][4], bf[8][2];
            #pragma unroll
            for (int mt = 0; mt < 2; mt++) {
                const float* p = Aw + (mt * 16 + g) * TKS + kk + tig;
                af[mt][0] = __float_as_uint(p[0]);
                af[mt][1] = __float_as_uint(p[8 * TKS]);
                af[mt][2] = __float_as_uint(p[4]);
                af[mt][3] = __float_as_uint(p[8 * TKS + 4]);
            }
            #pragma unroll
            for (int nt = 0; nt < 8; nt++) {
                const float* p = Bw + (nt * 8 + g) * TKS + kk + tig;
                bf[nt][0] = __float_as_uint(p[0]);
                bf[nt][1] = __float_as_uint(p[4]);
            }
            #pragma unroll
            for (int mt = 0; mt < 2; mt++)
                #pragma unroll
                for (int nt = 0; nt < 8; nt++)
                    mma_tf32(acc[mt][nt], af[mt], bf[nt]);
        }
    }

    // epilogue: bias + store (c0,c1 at row g; c2,c3 at row g+8; cols tig*2, tig*2+1)
    #pragma unroll
    for (int mt = 0; mt < 2; mt++) {
        long long r0 = rowTile + warp_m + mt * 16 + g;
        #pragma unroll
        for (int nt = 0; nt < 8; nt++) {
            int c0 = colTile + warp_n + nt * 8 + tig * 2;
            float b0 = bias[c0], b1 = bias[c0 + 1];
            float2 v0 = make_float2(acc[mt][nt][0] + b0, acc[mt][nt][1] + b1);
            float2 v1 = make_float2(acc[mt][nt][2] + b0, acc[mt][nt][3] + b1);
            *(float2*)&C[r0 * ldc + c0] = v0;
            *(float2*)&C[(r0 + 8) * ldc + c0] = v1;
        }
    }
}

// ---------------- weight transpose: Wt[n][k] = W[k][n] ----------------
__global__ __launch_bounds__(256)
void transpose_k(const float* __restrict__ W, int K, int N, float* __restrict__ Wt)
{
    __shared__ float t[32][33];
    int kb = blockIdx.y * 32, nb = blockIdx.x * 32;
    int tx = threadIdx.x & 31, ty = threadIdx.x >> 5;
    #pragma unroll
    for (int i = 0; i < 4; i++)
        t[ty + i * 8][tx] = W[(long long)(kb + ty + i * 8) * N + nb + tx];
    __syncthreads();
    #pragma unroll
    for (int i = 0; i < 4; i++)
        Wt[(long long)(nb + ty + i * 8) * K + kb + tx] = t[tx][ty + i * 8];
}

__global__ void biascat_kernel(const float* __restrict__ a, const float* __restrict__ b,
                               float* __restrict__ o)
{
    int i = blockIdx.x * 256 + threadIdx.x;
    if (i < 640) o[i] = a[i];
    else if (i < 1280) o[i] = b[i - 640];
}

// ---------------- fp32 SGEMM (stage-1 only, tiny K) ----------------
#define BM 128
#define BN_F 128
#define BK 16
__device__ __forceinline__ float2 ffma2(float2 a, float2 b, float2 c) {
    float2 d;
    asm("fma.rn.f32x2 %0, %1, %2, %3;"
        : "=l"(*(unsigned long long*)&d)
        : "l"(*(unsigned long long*)&a), "l"(*(unsigned long long*)&b), "l"(*(unsigned long long*)&c));
    return d;
}
__global__ __launch_bounds__(256, 2)
void sgemm(const float* __restrict__ A, int lda,
           const float* __restrict__ W, int ldw,
           const float* __restrict__ bias,
           float* __restrict__ C, int ldc, int K, int act)
{
    __shared__ float As[BK][BM + 1];
    __shared__ float Bs[BK][BN_F];
    const int tid = threadIdx.x;
    const int tx = tid & 15, ty = tid >> 4;
    const long long rowTile = (long long)blockIdx.y * BM;
    const int colTile = blockIdx.x * BN_F;
    float2 acc[8][4];
    #pragma unroll
    for (int i = 0; i < 8; i++)
        #pragma unroll
        for (int j = 0; j < 4; j++) acc[i][j] = make_float2(0.f, 0.f);
    for (int k0 = 0; k0 < K; k0 += BK) {
        #pragma unroll
        for (int i = 0; i < 8; i++) {
            int idx = tid + i * 256;
            int m = idx >> 4, kk = idx & 15;
            int kg = k0 + kk;
            As[kk][m] = (kg < K) ? A[(rowTile + m) * lda + kg] : 0.f;
        }
        #pragma unroll
        for (int i = 0; i < 8; i++) {
            int idx = tid + i * 256;
            int kk = idx >> 7, n = idx & 127;
            int kg = k0 + kk;
            Bs[kk][n] = (kg < K) ? W[(long long)kg * ldw + colTile + n] : 0.f;
        }
        __syncthreads();
        #pragma unroll
        for (int kk = 0; kk < BK; kk++) {
            float2 b[4]; float a[8];
            #pragma unroll
            for (int j = 0; j < 4; j++) b[j] = *(const float2*)&Bs[kk][tx * 2 + j * 32];
            #pragma unroll
            for (int i = 0; i < 8; i++) a[i] = As[kk][ty * 8 + i];
            #pragma unroll
            for (int i = 0; i < 8; i++) {
                float2 a2 = make_float2(a[i], a[i]);
                #pragma unroll
                for (int j = 0; j < 4; j++) acc[i][j] = ffma2(a2, b[j], acc[i][j]);
            }
        }
        __syncthreads();
    }
    #pragma unroll
    for (int i = 0; i < 8; i++) {
        long long row = rowTile + ty * 8 + i;
        #pragma unroll
        for (int j = 0; j < 4; j++) {
            int col = colTile + tx * 2 + j * 32;
            float2 v = acc[i][j];
            v.x += bias[col]; v.y += bias[col + 1];
            if (act == 1) { v.x = v.x * sigmoid_f(v.x); v.y = v.y * sigmoid_f(v.y); }
            *(float2*)&C[row * ldc + col] = v;
        }
    }
}

// ---------------- SE pooling / gating ----------------
__global__ __launch_bounds__(128)
void zsum_kernel(const float* __restrict__ z, float* __restrict__ zsum)
{
    int b = blockIdx.y;
    int c = blockIdx.x * 128 + threadIdx.x;
    const float* base = z + (long long)b * 2048 * 640 + c;
    float s0 = 0.f, s1 = 0.f, s2 = 0.f, s3 = 0.f;
    for (int t = 0; t < 2048; t += 4) {
        s0 += base[(long long)(t    ) * 640];
        s1 += base[(long long)(t + 1) * 640];
        s2 += base[(long long)(t + 2) * 640];
        s3 += base[(long long)(t + 3) * 640];
    }
    zsum[b * 640 + c] = (s0 + s1) + (s2 + s3);
}

__global__ __launch_bounds__(256)
void se_kernel(const float* __restrict__ zsum, const float* __restrict__ w1,
               const float* __restrict__ w2, float* __restrict__ se)
{
    int b = blockIdx.x;
    __shared__ float avg[640];
    __shared__ float r[160];
    for (int c = threadIdx.x; c < 640; c += 256)
        avg[c] = zsum[b * 640 + c] * (1.f / 2048.f);
    __syncthreads();
    for (int j = threadIdx.x; j < 160; j += 256) {
        float s = 0.f;
        for (int k = 0; k < 640; k++) s += avg[k] * w1[k * 160 + j];
        r[j] = fmaxf(s, 0.f);
    }
    __syncthreads();
    for (int j = threadIdx.x; j < 640; j += 256) {
        float s = 0.f;
        for (int k = 0; k < 160; k++) s += r[k] * w2[k * 640 + j];
        se[b * 640 + j] = sigmoid_f(s);
    }
}

__global__ __launch_bounds__(320)
void gate_ln_kernel(const float* __restrict__ z, const float* __restrict__ se,
                    const float* __restrict__ y,
                    const float* __restrict__ lnw, const float* __restrict__ lnb,
                    float* __restrict__ hout)
{
    long long row = blockIdx.x;
    const float* zr  = z  + row * 640;
    const float* yr  = y  + row * 1280;
    const float* ser = se + (int)(row >> TSEQ_SHIFT) * 640;
    __shared__ float hs[640];
    __shared__ float wsum[10], wsum2[10], stats[2];
    float s = 0.f, s2 = 0.f;
    #pragma unroll
    for (int u = 0; u < 2; u++) {
        int c = threadIdx.x + u * 320;
        float zse = zr[c] * ser[c];
        float gv = sigmoid_f(yr[c]);
        float pv = yr[640 + c];
        float h = gv * pv + (1.f - gv) * zse;
        hs[c] = h; s += h; s2 += h * h;
    }
    s = warp_sum(s); s2 = warp_sum(s2);
    int lane = threadIdx.x & 31, wid = threadIdx.x >> 5;
    if (lane == 0) { wsum[wid] = s; wsum2[wid] = s2; }
    __syncthreads();
    if (threadIdx.x == 0) {
        float a = 0.f, b2 = 0.f;
        #pragma unroll
        for (int i = 0; i < 10; i++) { a += wsum[i]; b2 += wsum2[i]; }
        float mu  = a * (1.f / 640.f);
        float var = b2 * (1.f / 640.f) - mu * mu;
        stats[0] = mu; stats[1] = rsqrtf(var + 1e-5f);
    }
    __syncthreads();
    float mu = stats[0], rs = stats[1];
    #pragma unroll
    for (int u = 0; u < 2; u++) {
        int c = threadIdx.x + u * 320;
        hout[row * 640 + c] = (hs[c] - mu) * rs * lnw[c] + lnb[c];
    }
}

// ---------------- GroupNorm ----------------
__global__ __launch_bounds__(256)
void gnstat_kernel(const float* __restrict__ out, float* __restrict__ gst)
{
    int b = blockIdx.y, g = blockIdx.x;
    const float* base = out + (long long)b * 2048 * 512 + g * 64;
    float s = 0.f, s2 = 0.f;
    for (int idx = threadIdx.x; idx < 2048 * 64; idx += 256) {
        int t = idx >> 6, c = idx & 63;
        float v = base[(long long)t * 512 + c];
        s += v; s2 += v * v;
    }
    s = warp_sum(s); s2 = warp_sum(s2);
    __shared__ float a[8], a2[8];
    int lane = threadIdx.x & 31, wid = threadIdx.x >> 5;
    if (lane == 0) { a[wid] = s; a2[wid] = s2; }
    __syncthreads();
    if (threadIdx.x == 0) {
        float S = 0.f, S2 = 0.f;
        #pragma unroll
        for (int i = 0; i < 8; i++) { S += a[i]; S2 += a2[i]; }
        double mean = (double)S / 131072.0;
        double var  = (double)S2 / 131072.0 - mean * mean;
        gst[(b * 8 + g) * 2 + 0] = (float)mean;
        gst[(b * 8 + g) * 2 + 1] = (float)rsqrt(var + 1e-5);
    }
}

__global__ __launch_bounds__(256)
void gnapply_kernel(const float* __restrict__ out, const float* __restrict__ gst,
                    const float* __restrict__ gw, const float* __restrict__ gb,
                    float* __restrict__ dst)
{
    const long long total = (long long)NTOK * 128;
    for (long long i = (long long)blockIdx.x * blockDim.x + threadIdx.x;
         i < total; i += (long long)gridDim.x * blockDim.x) {
        long long row = i >> 7;
        int q = (int)(i & 127);
        int d = q * 4;
        int b = (int)(row >> TSEQ_SHIFT);
        int g = d >> 6;
        float mean = gst[(b * 8 + g) * 2 + 0];
        float rs   = gst[(b * 8 + g) * 2 + 1];
        float4 v  = *(const float4*)&out[(row << 9) + d];
        float4 w  = *(const float4*)&gw[d];
        float4 bb = *(const float4*)&gb[d];
        float4 r;
        r.x = (v.x - mean) * rs * w.x + bb.x;
        r.y = (v.y - mean) * rs * w.y + bb.y;
        r.z = (v.z - mean) * rs * w.z + bb.z;
        r.w = (v.w - mean) * rs * w.w + bb.w;
        *(float4*)&dst[(row << 9) + d] = r;
    }
}

// ---------------- launch ----------------
extern "C" void kernel_launch(void* const* d_in, const int* in_sizes, int n_in,
                              void* d_out, int out_size)
{
    const float* x    = (const float*)d_in[0];
    const float* hw1  = (const float*)d_in[1];
    const float* hb1  = (const float*)d_in[2];
    const float* hw2  = (const float*)d_in[3];
    const float* hb2  = (const float*)d_in[4];
    const float* lw1  = (const float*)d_in[5];
    const float* lb1  = (const float*)d_in[6];
    const float* lw2  = (const float*)d_in[7];
    const float* lb2  = (const float*)d_in[8];
    const float* ew1  = (const float*)d_in[9];
    const float* eb1  = (const float*)d_in[10];
    const float* ew2  = (const float*)d_in[11];
    const float* eb2  = (const float*)d_in[12];
    const float* sew1 = (const float*)d_in[13];
    const float* sew2 = (const float*)d_in[14];
    const float* gwv  = (const float*)d_in[15];
    const float* gbv  = (const float*)d_in[16];
    const float* pwv  = (const float*)d_in[17];
    const float* pbv  = (const float*)d_in[18];
    const float* lnw  = (const float*)d_in[19];
    const float* lnb  = (const float*)d_in[20];
    const float* owv  = (const float*)d_in[21];
    const float* obv  = (const float*)d_in[22];
    const float* gnw  = (const float*)d_in[23];
    const float* gnb  = (const float*)d_in[24];
    float* dst = (float*)d_out;

    float *a1, *z, *y, *ob, *zs, *se, *gn, *wty, *wto, *wth, *wtl, *wte, *by;
    cudaGetSymbolAddress((void**)&a1, g_a1);
    cudaGetSymbolAddress((void**)&z,  g_z);
    cudaGetSymbolAddress((void**)&y,  g_y);
    cudaGetSymbolAddress((void**)&ob, g_o);
    cudaGetSymbolAddress((void**)&zs, g_zsum);
    cudaGetSymbolAddress((void**)&se, g_se);
    cudaGetSymbolAddress((void**)&gn, g_gn);
    cudaGetSymbolAddress((void**)&wty, g_wty);
    cudaGetSymbolAddress((void**)&wto, g_wto);
    cudaGetSymbolAddress((void**)&wth, g_wth);
    cudaGetSymbolAddress((void**)&wtl, g_wtl);
    cudaGetSymbolAddress((void**)&wte, g_wte);
    cudaGetSymbolAddress((void**)&by,  g_by);

    // weight transposes + bias concat (tiny)
    transpose_k<<<dim3(640 / 32, 640 / 32), 256>>>(gwv, 640, 640, wty);
    transpose_k<<<dim3(640 / 32, 640 / 32), 256>>>(pwv, 640, 640, wty + 640 * 640);
    transpose_k<<<dim3(512 / 32, 640 / 32), 256>>>(owv, 640, 512, wto);
    transpose_k<<<dim3(256 / 32, 256 / 32), 256>>>(hw2, 256, 256, wth);
    transpose_k<<<dim3(256 / 32, 256 / 32), 256>>>(lw2, 256, 256, wtl);
    transpose_k<<<dim3(128 / 32, 128 / 32), 256>>>(ew2, 128, 128, wte);
    biascat_kernel<<<5, 256>>>(gbv, pbv, by);

    const dim3 blk(256);
    const int MY = NTOK / 128;  // 1024 row tiles

    // stage 1 (fp32 FFMA, tiny K): a1 = silu(x_slice @ w1 + b1)
    sgemm<<<dim3(2, MY), blk>>>(x +  0, 44, hw1, 256, hb1, a1 +   0, 640, 14, 1);
    sgemm<<<dim3(2, MY), blk>>>(x + 14, 44, lw1, 256, lb1, a1 + 256, 640, 22, 1);
    sgemm<<<dim3(1, MY), blk>>>(x + 36, 44, ew1, 128, eb1, a1 + 512, 640,  8, 1);

    // stage 2 (tf32 mma.sync): z = a1_branch @ w2 + b2
    mma_gemm<<<dim3(2, MY), blk>>>(a1 +   0, 640, wth, hb2, z +   0, 640, 256, nullptr);
    mma_gemm<<<dim3(2, MY), blk>>>(a1 + 256, 640, wtl, lb2, z + 256, 640, 256, nullptr);
    mma_gemm<<<dim3(1, MY), blk>>>(a1 + 512, 640, wte, eb2, z + 512, 640, 128, nullptr);

    // SE path
    zsum_kernel<<<dim3(5, 64), 128>>>(z, zs);
    se_kernel<<<64, 256>>>(zs, sew1, sew2, se);

    // stage 3 (tf32, SE fused in A load): y = (z*se) @ [gw|pw] + [gb|pb]
    mma_gemm<<<dim3(10, MY), blk>>>(z, 640, wty, by, y, 1280, 640, se);

    // gate + LayerNorm -> h (reuse a1)
    gate_ln_kernel<<<NTOK, 320>>>(z, se, y, lnw, lnb, a1);

    // output projection (tf32)
    mma_gemm<<<dim3(4, MY), blk>>>(a1, 640, wto, obv, ob, 512, 640, nullptr);

    // GroupNorm(8)
    gnstat_kernel<<<dim3(8, 64), 256>>>(ob, gn);
    gnapply_kernel<<<2048, 256>>>(ob, gn, gnw, gnb, dst);
}

// round 8
// speedup vs baseline: 3.6842x; 1.7425x over previous
#include <cuda_runtime.h>
#include <cuda_fp16.h>
#include <cstdint>
#include <math.h>

// ---------------- problem constants ----------------
#define NTOK   131072
#define TSEQ_SHIFT 11          // T = 2048
#define DCOMB  640
#define DOUT   512

// ---------------- scratch ----------------
__device__ __half g_a1h [(long long)NTOK * 640];   // stage-1 out (fp16, GEMM input)
__device__ __half g_zseh[(long long)NTOK * 640];   // z*se (fp16, GEMM input)
__device__ __half g_hh  [(long long)NTOK * 640];   // post-LN h (fp16, GEMM input)
__device__ float  g_z   [(long long)NTOK * 640];   // z fp32 (SE + gate path)
__device__ float  g_y   [(long long)NTOK * 1280];  // [gate | p] preacts fp32
__device__ float  g_o   [(long long)NTOK * 512];   // pre-GroupNorm out
__device__ float  g_zsum[64 * 640];
__device__ float  g_se  [64 * 640];
__device__ float  g_gn  [64 * 8 * 2];
// transposed fp16 weights [N][K] + concatenated fp32 bias
__device__ __half g_wty[1280 * 640];
__device__ __half g_wto[512 * 640];
__device__ __half g_wth[256 * 256];
__device__ __half g_wtl[256 * 256];
__device__ __half g_wte[128 * 128];
__device__ float  g_by [1280];

// ---------------- helpers ----------------
__device__ __forceinline__ uint32_t smem_u32(const void* p) {
    uint32_t a;
    asm("{ .reg .u64 t; cvta.to.shared.u64 t, %1; cvt.u32.u64 %0, t; }" : "=r"(a) : "l"(p));
    return a;
}
__device__ __forceinline__ float warp_sum(float v) {
    #pragma unroll
    for (int o = 16; o > 0; o >>= 1) v += __shfl_down_sync(0xffffffffu, v, o);
    return v;
}
__device__ __forceinline__ float sigmoid_f(float x) { return 1.f / (1.f + __expf(-x)); }

#define CP_ASYNC16(dst, src) \
    asm volatile("cp.async.cg.shared.global [%0], [%1], 16;" :: "r"(dst), "l"(src))
#define CP_COMMIT()  asm volatile("cp.async.commit_group;" ::: "memory")
#define CP_WAIT2()   asm volatile("cp.async.wait_group 2;" ::: "memory")

__device__ __forceinline__ void ldsm_x4(uint32_t& r0, uint32_t& r1, uint32_t& r2, uint32_t& r3,
                                        uint32_t addr) {
    asm volatile("ldmatrix.sync.aligned.m8n8.x4.shared.b16 {%0,%1,%2,%3}, [%4];"
                 : "=r"(r0), "=r"(r1), "=r"(r2), "=r"(r3) : "r"(addr));
}
__device__ __forceinline__ void mma_f16(float* c, const uint32_t* a, const uint32_t* b) {
    asm volatile(
        "mma.sync.aligned.m16n8k16.row.col.f32.f16.f16.f32 "
        "{%0,%1,%2,%3}, {%4,%5,%6,%7}, {%8,%9}, {%0,%1,%2,%3};"
        : "+f"(c[0]), "+f"(c[1]), "+f"(c[2]), "+f"(c[3])
        : "r"(a[0]), "r"(a[1]), "r"(a[2]), "r"(a[3]), "r"(b[0]), "r"(b[1]));
}

// ---------------- fp16 tensor-core GEMM, cp.async 4-stage pipeline ----------------
// C[M,N](fp32) = A[M,K](fp16) @ Wt[N,K](fp16)^T + bias
// Block 128(M)x128(N)xBK=32, 256 thr = 8 warps, warp tile 32x64. K % 32 == 0, K >= 128.
#define HST 40     // padded smem row stride in halves (80B, 16B-aligned, ldmatrix conflict-free)
#define STG 4

__global__ __launch_bounds__(256, 2)
void hgemm(const __half* __restrict__ A, int lda,
           const __half* __restrict__ Wt,
           const float* __restrict__ bias,
           float* __restrict__ C, int ldc, int K)
{
    extern __shared__ __half sh[];
    const uint32_t sbase = smem_u32(sh);
    const uint32_t BOFF  = STG * 128 * HST;      // B region offset (halves)

    const int tid  = threadIdx.x;
    const int wid  = tid >> 5;
    const int lane = tid & 31;
    const int warp_m = (wid & 3) * 32;
    const int warp_n = (wid >> 2) * 64;
    const long long rowTile = (long long)blockIdx.y * 128;
    const int colTile = blockIdx.x * 128;

    // producer mapping: 2 threads per row, 2 x 16B chunks each (row = 32 halves = 64B)
    const int pr = tid >> 1;
    const int pc = (tid & 1) * 2;
    const __half* Abase = A + (rowTile + pr) * lda;
    const __half* Bbase = Wt + (long long)(colTile + pr) * K;
    const uint32_t aDst0 = sbase + (uint32_t)(pr * HST) * 2;
    const uint32_t bDst0 = sbase + (uint32_t)(BOFF + pr * HST) * 2;

    const int nk = K >> 5;

    float acc[2][8][4];
    #pragma unroll
    for (int mt = 0; mt < 2; mt++)
        #pragma unroll
        for (int nt = 0; nt < 8; nt++)
            #pragma unroll
            for (int i = 0; i < 4; i++) acc[mt][nt][i] = 0.f;

    auto issue = [&](int kt) {
        const int s = kt & (STG - 1);
        const uint32_t so = (uint32_t)(s * 128 * HST) * 2;
        const __half* ag = Abase + (kt << 5);
        const __half* bg = Bbase + (kt << 5);
        CP_ASYNC16(aDst0 + so + (pc    ) * 16, ag + (pc    ) * 8);
        CP_ASYNC16(aDst0 + so + (pc + 1) * 16, ag + (pc + 1) * 8);
        CP_ASYNC16(bDst0 + so + (pc    ) * 16, bg + (pc    ) * 8);
        CP_ASYNC16(bDst0 + so + (pc + 1) * 16, bg + (pc + 1) * 8);
        CP_COMMIT();
    };

    issue(0); issue(1); issue(2);

    // fragment lane decode
    const int a_r = lane & 15, a_h = lane >> 4;          // A: row, k-half
    const int b_r = lane & 7, b_k = (lane >> 3) & 1, b_n = (lane >> 4) & 1;  // B

    for (int kt = 0; kt < nk; kt++) {
        CP_WAIT2();
        __syncthreads();
        if (kt + 3 < nk) issue(kt + 3); else CP_COMMIT();

        const int s = kt & (STG - 1);
        const uint32_t aS = sbase + (uint32_t)((s * 128 + warp_m) * HST) * 2;
        const uint32_t bS = sbase + (uint32_t)(BOFF + (s * 128 + warp_n) * HST) * 2;

        #pragma unroll
        for (int ks = 0; ks < 2; ks++) {
            uint32_t af[2][4], bf[8][2];
            #pragma unroll
            for (int mt = 0; mt < 2; mt++)
                ldsm_x4(af[mt][0], af[mt][1], af[mt][2], af[mt][3],
                        aS + (uint32_t)((mt * 16 + a_r) * HST + ks * 16 + a_h * 8) * 2);
            #pragma unroll
            for (int p = 0; p < 4; p++)
                ldsm_x4(bf[2 * p][0], bf[2 * p][1], bf[2 * p + 1][0], bf[2 * p + 1][1],
                        bS + (uint32_t)((p * 16 + b_n * 8 + b_r) * HST + ks * 16 + b_k * 8) * 2);
            #pragma unroll
            for (int mt = 0; mt < 2; mt++)
                #pragma unroll
                for (int nt = 0; nt < 8; nt++)
                    mma_f16(acc[mt][nt], af[mt], bf[nt]);
        }
    }

    // epilogue: c0,c1 -> row g cols tig*2; c2,c3 -> row g+8
    const int g = lane >> 2, tig = lane & 3;
    #pragma unroll
    for (int mt = 0; mt < 2; mt++) {
        long long r0 = rowTile + warp_m + mt * 16 + g;
        #pragma unroll
        for (int nt = 0; nt < 8; nt++) {
            int c0 = colTile + warp_n + nt * 8 + tig * 2;
            float b0 = __ldg(bias + c0), b1 = __ldg(bias + c0 + 1);
            *(float2*)&C[r0 * ldc + c0] = make_float2(acc[mt][nt][0] + b0, acc[mt][nt][1] + b1);
            *(float2*)&C[(r0 + 8) * ldc + c0] = make_float2(acc[mt][nt][2] + b0, acc[mt][nt][3] + b1);
        }
    }
}

// ---------------- weight transpose + fp16 convert: Wt[n][k] = half(W[k][n]) ----------------
__global__ __launch_bounds__(256)
void transpose_k(const float* __restrict__ W, int K, int N, __half* __restrict__ Wt)
{
    __shared__ float t[32][33];
    int kb = blockIdx.y * 32, nb = blockIdx.x * 32;
    int tx = threadIdx.x & 31, ty = threadIdx.x >> 5;
    #pragma unroll
    for (int i = 0; i < 4; i++)
        t[ty + i * 8][tx] = W[(long long)(kb + ty + i * 8) * N + nb + tx];
    __syncthreads();
    #pragma unroll
    for (int i = 0; i < 4; i++)
        Wt[(long long)(nb + ty + i * 8) * K + kb + tx] = __float2half_rn(t[tx][ty + i * 8]);
}

__global__ void biascat_kernel(const float* __restrict__ a, const float* __restrict__ b,
                               float* __restrict__ o)
{
    int i = blockIdx.x * 256 + threadIdx.x;
    if (i < 640) o[i] = a[i];
    else if (i < 1280) o[i] = b[i - 640];
}

// ---------------- fp32 SGEMM (stage-1 only, tiny K), writes fp16 ----------------
#define BM 128
#define BN_F 128
#define BK 16
__device__ __forceinline__ float2 ffma2(float2 a, float2 b, float2 c) {
    float2 d;
    asm("fma.rn.f32x2 %0, %1, %2, %3;"
        : "=l"(*(unsigned long long*)&d)
        : "l"(*(unsigned long long*)&a), "l"(*(unsigned long long*)&b), "l"(*(unsigned long long*)&c));
    return d;
}
__global__ __launch_bounds__(256, 2)
void sgemm_h(const float* __restrict__ A, int lda,
             const float* __restrict__ W, int ldw,
             const float* __restrict__ bias,
             __half* __restrict__ C, int ldc, int K)
{
    __shared__ float As[BK][BM + 1];
    __shared__ float Bs[BK][BN_F];
    const int tid = threadIdx.x;
    const int tx = tid & 15, ty = tid >> 4;
    const long long rowTile = (long long)blockIdx.y * BM;
    const int colTile = blockIdx.x * BN_F;
    float2 acc[8][4];
    #pragma unroll
    for (int i = 0; i < 8; i++)
        #pragma unroll
        for (int j = 0; j < 4; j++) acc[i][j] = make_float2(0.f, 0.f);
    for (int k0 = 0; k0 < K; k0 += BK) {
        #pragma unroll
        for (int i = 0; i < 8; i++) {
            int idx = tid + i * 256;
            int m = idx >> 4, kk = idx & 15;
            int kg = k0 + kk;
            As[kk][m] = (kg < K) ? A[(rowTile + m) * lda + kg] : 0.f;
        }
        #pragma unroll
        for (int i = 0; i < 8; i++) {
            int idx = tid + i * 256;
            int kk = idx >> 7, n = idx & 127;
            int kg = k0 + kk;
            Bs[kk][n] = (kg < K) ? W[(long long)kg * ldw + colTile + n] : 0.f;
        }
        __syncthreads();
        #pragma unroll
        for (int kk = 0; kk < BK; kk++) {
            float2 b[4]; float a[8];
            #pragma unroll
            for (int j = 0; j < 4; j++) b[j] = *(const float2*)&Bs[kk][tx * 2 + j * 32];
            #pragma unroll
            for (int i = 0; i < 8; i++) a[i] = As[kk][ty * 8 + i];
            #pragma unroll
            for (int i = 0; i < 8; i++) {
                float2 a2 = make_float2(a[i], a[i]);
                #pragma unroll
                for (int j = 0; j < 4; j++) acc[i][j] = ffma2(a2, b[j], acc[i][j]);
            }
        }
        __syncthreads();
    }
    #pragma unroll
    for (int i = 0; i < 8; i++) {
        long long row = rowTile + ty * 8 + i;
        #pragma unroll
        for (int j = 0; j < 4; j++) {
            int col = colTile + tx * 2 + j * 32;
            float vx = acc[i][j].x + bias[col];
            float vy = acc[i][j].y + bias[col + 1];
            vx = vx * sigmoid_f(vx);             // SiLU
            vy = vy * sigmoid_f(vy);
            *(__half2*)&C[row * ldc + col] = __floats2half2_rn(vx, vy);
        }
    }
}

// ---------------- SE pooling / gating ----------------
__global__ __launch_bounds__(128)
void zsum_kernel(const float* __restrict__ z, float* __restrict__ zsum)
{
    int b = blockIdx.y;
    int c = blockIdx.x * 128 + threadIdx.x;
    const float* base = z + (long long)b * 2048 * 640 + c;
    float s0 = 0.f, s1 = 0.f, s2 = 0.f, s3 = 0.f;
    for (int t = 0; t < 2048; t += 4) {
        s0 += base[(long long)(t    ) * 640];
        s1 += base[(long long)(t + 1) * 640];
        s2 += base[(long long)(t + 2) * 640];
        s3 += base[(long long)(t + 3) * 640];
    }
    zsum[b * 640 + c] = (s0 + s1) + (s2 + s3);
}

__global__ __launch_bounds__(256)
void se_kernel(const float* __restrict__ zsum, const float* __restrict__ w1,
               const float* __restrict__ w2, float* __restrict__ se)
{
    int b = blockIdx.x;
    __shared__ float avg[640];
    __shared__ float r[160];
    for (int c = threadIdx.x; c < 640; c += 256)
        avg[c] = zsum[b * 640 + c] * (1.f / 2048.f);
    __syncthreads();
    for (int j = threadIdx.x; j < 160; j += 256) {
        float s = 0.f;
        for (int k = 0; k < 640; k++) s += avg[k] * w1[k * 160 + j];
        r[j] = fmaxf(s, 0.f);
    }
    __syncthreads();
    for (int j = threadIdx.x; j < 640; j += 256) {
        float s = 0.f;
        for (int k = 0; k < 160; k++) s += r[k] * w2[k * 640 + j];
        se[b * 640 + j] = sigmoid_f(s);
    }
}

// z_se = z * se[batch] -> fp16 (GEMM input), fp32 math, one rounding
__global__ __launch_bounds__(256)
void zse_kernel(const float* __restrict__ z, const float* __restrict__ se,
                __half* __restrict__ out)
{
    const long long total = (long long)NTOK * 160;   // float4 groups
    for (long long i = (long long)blockIdx.x * blockDim.x + threadIdx.x;
         i < total; i += (long long)gridDim.x * blockDim.x) {
        long long row = i / 160;
        int q = (int)(i - row * 160);
        int b = (int)(row >> TSEQ_SHIFT);
        float4 zv = *(const float4*)&z[row * 640 + q * 4];
        float4 sv = *(const float4*)&se[b * 640 + q * 4];
        __half2 h0 = __floats2half2_rn(zv.x * sv.x, zv.y * sv.y);
        __half2 h1 = __floats2half2_rn(zv.z * sv.z, zv.w * sv.w);
        uint2 pk = make_uint2(*(uint32_t*)&h0, *(uint32_t*)&h1);
        *(uint2*)&out[row * 640 + q * 4] = pk;
    }
}

__global__ __launch_bounds__(320)
void gate_ln_kernel(const float* __restrict__ z, const float* __restrict__ se,
                    const float* __restrict__ y,
                    const float* __restrict__ lnw, const float* __restrict__ lnb,
                    __half* __restrict__ hout)
{
    long long row = blockIdx.x;
    const float* zr  = z  + row * 640;
    const float* yr  = y  + row * 1280;
    const float* ser = se + (int)(row >> TSEQ_SHIFT) * 640;
    __shared__ float hs[640];
    __shared__ float wsum[10], wsum2[10], stats[2];
    float s = 0.f, s2 = 0.f;
    #pragma unroll
    for (int u = 0; u < 2; u++) {
        int c = threadIdx.x + u * 320;
        float zse = zr[c] * ser[c];
        float gv = sigmoid_f(yr[c]);
        float pv = yr[640 + c];
        float h = gv * pv + (1.f - gv) * zse;
        hs[c] = h; s += h; s2 += h * h;
    }
    s = warp_sum(s); s2 = warp_sum(s2);
    int lane = threadIdx.x & 31, wid = threadIdx.x >> 5;
    if (lane == 0) { wsum[wid] = s; wsum2[wid] = s2; }
    __syncthreads();
    if (threadIdx.x == 0) {
        float a = 0.f, b2 = 0.f;
        #pragma unroll
        for (int i = 0; i < 10; i++) { a += wsum[i]; b2 += wsum2[i]; }
        float mu  = a * (1.f / 640.f);
        float var = b2 * (1.f / 640.f) - mu * mu;
        stats[0] = mu; stats[1] = rsqrtf(var + 1e-5f);
    }
    __syncthreads();
    float mu = stats[0], rs = stats[1];
    #pragma unroll
    for (int u = 0; u < 2; u++) {
        int c = threadIdx.x + u * 320;
        hout[row * 640 + c] = __float2half_rn((hs[c] - mu) * rs * lnw[c] + lnb[c]);
    }
}

// ---------------- GroupNorm ----------------
__global__ __launch_bounds__(256)
void gnstat_kernel(const float* __restrict__ out, float* __restrict__ gst)
{
    int b = blockIdx.y, g = blockIdx.x;
    const float* base = out + (long long)b * 2048 * 512 + g * 64;
    float s = 0.f, s2 = 0.f;
    for (int idx = threadIdx.x; idx < 2048 * 64; idx += 256) {
        int t = idx >> 6, c = idx & 63;
        float v = base[(long long)t * 512 + c];
        s += v; s2 += v * v;
    }
    s = warp_sum(s); s2 = warp_sum(s2);
    __shared__ float a[8], a2[8];
    int lane = threadIdx.x & 31, wid = threadIdx.x >> 5;
    if (lane == 0) { a[wid] = s; a2[wid] = s2; }
    __syncthreads();
    if (threadIdx.x == 0) {
        float S = 0.f, S2 = 0.f;
        #pragma unroll
        for (int i = 0; i < 8; i++) { S += a[i]; S2 += a2[i]; }
        double mean = (double)S / 131072.0;
        double var  = (double)S2 / 131072.0 - mean * mean;
        gst[(b * 8 + g) * 2 + 0] = (float)mean;
        gst[(b * 8 + g) * 2 + 1] = (float)rsqrt(var + 1e-5);
    }
}

__global__ __launch_bounds__(256)
void gnapply_kernel(const float* __restrict__ out, const float* __restrict__ gst,
                    const float* __restrict__ gw, const float* __restrict__ gb,
                    float* __restrict__ dst)
{
    const long long total = (long long)NTOK * 128;
    for (long long i = (long long)blockIdx.x * blockDim.x + threadIdx.x;
         i < total; i += (long long)gridDim.x * blockDim.x) {
        long long row = i >> 7;
        int q = (int)(i & 127);
        int d = q * 4;
        int b = (int)(row >> TSEQ_SHIFT);
        int g = d >> 6;
        float mean = gst[(b * 8 + g) * 2 + 0];
        float rs   = gst[(b * 8 + g) * 2 + 1];
        float4 v  = *(const float4*)&out[(row << 9) + d];
        float4 w  = *(const float4*)&gw[d];
        float4 bb = *(const float4*)&gb[d];
        float4 r;
        r.x = (v.x - mean) * rs * w.x + bb.x;
        r.y = (v.y - mean) * rs * w.y + bb.y;
        r.z = (v.z - mean) * rs * w.z + bb.z;
        r.w = (v.w - mean) * rs * w.w + bb.w;
        *(float4*)&dst[(row << 9) + d] = r;
    }
}

// ---------------- launch ----------------
extern "C" void kernel_launch(void* const* d_in, const int* in_sizes, int n_in,
                              void* d_out, int out_size)
{
    const float* x    = (const float*)d_in[0];
    const float* hw1  = (const float*)d_in[1];
    const float* hb1  = (const float*)d_in[2];
    const float* hw2  = (const float*)d_in[3];
    const float* hb2  = (const float*)d_in[4];
    const float* lw1  = (const float*)d_in[5];
    const float* lb1  = (const float*)d_in[6];
    const float* lw2  = (const float*)d_in[7];
    const float* lb2  = (const float*)d_in[8];
    const float* ew1  = (const float*)d_in[9];
    const float* eb1  = (const float*)d_in[10];
    const float* ew2  = (const float*)d_in[11];
    const float* eb2  = (const float*)d_in[12];
    const float* sew1 = (const float*)d_in[13];
    const float* sew2 = (const float*)d_in[14];
    const float* gwv  = (const float*)d_in[15];
    const float* gbv  = (const float*)d_in[16];
    const float* pwv  = (const float*)d_in[17];
    const float* pbv  = (const float*)d_in[18];
    const float* lnw  = (const float*)d_in[19];
    const float* lnb  = (const float*)d_in[20];
    const float* owv  = (const float*)d_in[21];
    const float* obv  = (const float*)d_in[22];
    const float* gnw  = (const float*)d_in[23];
    const float* gnb  = (const float*)d_in[24];
    float* dst = (float*)d_out;

    __half *a1h, *zseh, *hh, *wty, *wto, *wth, *wtl, *wte;
    float *z, *y, *ob, *zs, *se, *gn, *by;
    cudaGetSymbolAddress((void**)&a1h,  g_a1h);
    cudaGetSymbolAddress((void**)&zseh, g_zseh);
    cudaGetSymbolAddress((void**)&hh,   g_hh);
    cudaGetSymbolAddress((void**)&z,  g_z);
    cudaGetSymbolAddress((void**)&y,  g_y);
    cudaGetSymbolAddress((void**)&ob, g_o);
    cudaGetSymbolAddress((void**)&zs, g_zsum);
    cudaGetSymbolAddress((void**)&se, g_se);
    cudaGetSymbolAddress((void**)&gn, g_gn);
    cudaGetSymbolAddress((void**)&wty, g_wty);
    cudaGetSymbolAddress((void**)&wto, g_wto);
    cudaGetSymbolAddress((void**)&wth, g_wth);
    cudaGetSymbolAddress((void**)&wtl, g_wtl);
    cudaGetSymbolAddress((void**)&wte, g_wte);
    cudaGetSymbolAddress((void**)&by,  g_by);

    const int HSMEM = STG * 128 * HST * 2 * 2;   // 81920 bytes (A + B regions)
    cudaFuncSetAttribute(hgemm, cudaFuncAttributeMaxDynamicSharedMemorySize, HSMEM);

    // weight transposes (fp32 -> fp16 [N][K]) + bias concat
    transpose_k<<<dim3(640 / 32, 640 / 32), 256>>>(gwv, 640, 640, wty);
    transpose_k<<<dim3(640 / 32, 640 / 32), 256>>>(pwv, 640, 640, wty + 640 * 640);
    transpose_k<<<dim3(512 / 32, 640 / 32), 256>>>(owv, 640, 512, wto);
    transpose_k<<<dim3(256 / 32, 256 / 32), 256>>>(hw2, 256, 256, wth);
    transpose_k<<<dim3(256 / 32, 256 / 32), 256>>>(lw2, 256, 256, wtl);
    transpose_k<<<dim3(128 / 32, 128 / 32), 256>>>(ew2, 128, 128, wte);
    biascat_kernel<<<5, 256>>>(gbv, pbv, by);

    const dim3 blk(256);
    const int MY = NTOK / 128;  // 1024 row tiles

    // stage 1 (fp32 FFMA, tiny K) -> fp16 a1
    sgemm_h<<<dim3(2, MY), blk>>>(x +  0, 44, hw1, 256, hb1, a1h +   0, 640, 14);
    sgemm_h<<<dim3(2, MY), blk>>>(x + 14, 44, lw1, 256, lb1, a1h + 256, 640, 22);
    sgemm_h<<<dim3(1, MY), blk>>>(x + 36, 44, ew1, 128, eb1, a1h + 512, 640,  8);

    // stage 2 (fp16 HMMA): z = a1_branch @ w2 + b2  (fp32 out)
    hgemm<<<dim3(2, MY), blk, HSMEM>>>(a1h +   0, 640, wth, hb2, z +   0, 640, 256);
    hgemm<<<dim3(2, MY), blk, HSMEM>>>(a1h + 256, 640, wtl, lb2, z + 256, 640, 256);
    hgemm<<<dim3(1, MY), blk, HSMEM>>>(a1h + 512, 640, wte, eb2, z + 512, 640, 128);

    // SE path
    zsum_kernel<<<dim3(5, 64), 128>>>(z, zs);
    se_kernel<<<64, 256>>>(zs, sew1, sew2, se);
    zse_kernel<<<2048, 256>>>(z, se, zseh);

    // stage 3 (fp16 HMMA): y = z_se @ [gw|pw] + [gb|pb]
    hgemm<<<dim3(10, MY), blk, HSMEM>>>(zseh, 640, wty, by, y, 1280, 640);

    // gate + LayerNorm -> fp16 h
    gate_ln_kernel<<<NTOK, 320>>>(z, se, y, lnw, lnb, hh);

    // output projection (fp16 HMMA)
    hgemm<<<dim3(4, MY), blk, HSMEM>>>(hh, 640, wto, obv, ob, 512, 640);

    // GroupNorm(8)
    gnstat_kernel<<<dim3(8, 64), 256>>>(ob, gn);
    gnapply_kernel<<<2048, 256>>>(ob, gn, gnw, gnb, dst);
}

// round 12
// speedup vs baseline: 3.9587x; 1.0745x over previous
#include <cuda_runtime.h>
#include <cuda_fp16.h>
#include <cstdint>
#include <math.h>

// ---------------- problem constants ----------------
#define NTOK   131072
#define TSEQ_SHIFT 11          // T = 2048
#define DCOMB  640
#define DOUT   512

// ---------------- scratch ----------------
__device__ __half g_a1h [(long long)NTOK * 640];   // stage-1 out (fp16)
__device__ __half g_zh  [(long long)NTOK * 640];   // z (fp16)
__device__ __half g_zseh[(long long)NTOK * 640];   // z*se (fp16)
__device__ __half g_yh  [(long long)NTOK * 1280];  // [gate | p] preacts (fp16)
__device__ __half g_hh  [(long long)NTOK * 640];   // post-LN h (fp16)
__device__ float  g_o   [(long long)NTOK * 512];   // pre-GroupNorm out (fp32)
__device__ float  g_zsum[64 * 640];                // fused SE column sums
__device__ float  g_se  [64 * 640];
__device__ float  g_gnp [64 * 8 * 2];              // GN partial (sum, sumsq)
__device__ float  g_gn  [64 * 8 * 2];              // GN (mean, rstd)
// transposed fp16 weights [N][K] + concatenated fp32 bias
__device__ __half g_wty[1280 * 640];
__device__ __half g_wto[512 * 640];
__device__ __half g_wth[256 * 256];
__device__ __half g_wtl[256 * 256];
__device__ __half g_wte[128 * 128];
__device__ float  g_by [1280];

// ---------------- helpers ----------------
__device__ __forceinline__ uint32_t smem_u32(const void* p) {
    uint32_t a;
    asm("{ .reg .u64 t; cvta.to.shared.u64 t, %1; cvt.u32.u64 %0, t; }" : "=r"(a) : "l"(p));
    return a;
}
__device__ __forceinline__ float warp_sum(float v) {
    #pragma unroll
    for (int o = 16; o > 0; o >>= 1) v += __shfl_down_sync(0xffffffffu, v, o);
    return v;
}
__device__ __forceinline__ float sigmoid_f(float x) { return 1.f / (1.f + __expf(-x)); }

#define CP_ASYNC16(dst, src) \
    asm volatile("cp.async.cg.shared.global [%0], [%1], 16;" :: "r"(dst), "l"(src))
#define CP_COMMIT()  asm volatile("cp.async.commit_group;" ::: "memory")
#define CP_WAIT2()   asm volatile("cp.async.wait_group 2;" ::: "memory")

__device__ __forceinline__ void ldsm_x4(uint32_t& r0, uint32_t& r1, uint32_t& r2, uint32_t& r3,
                                        uint32_t addr) {
    asm volatile("ldmatrix.sync.aligned.m8n8.x4.shared.b16 {%0,%1,%2,%3}, [%4];"
                 : "=r"(r0), "=r"(r1), "=r"(r2), "=r"(r3) : "r"(addr));
}
__device__ __forceinline__ void mma_f16(float* c, const uint32_t* a, const uint32_t* b) {
    asm volatile(
        "mma.sync.aligned.m16n8k16.row.col.f32.f16.f16.f32 "
        "{%0,%1,%2,%3}, {%4,%5,%6,%7}, {%8,%9}, {%0,%1,%2,%3};"
        : "+f"(c[0]), "+f"(c[1]), "+f"(c[2]), "+f"(c[3])
        : "r"(a[0]), "r"(a[1]), "r"(a[2]), "r"(a[3]), "r"(b[0]), "r"(b[1]));
}

// ---------------- fp16 tensor-core GEMM, cp.async 4-stage pipeline ----------------
// C[M,N] = A[M,K](fp16) @ Wt[N,K](fp16)^T + bias
// Block 128x128xBK=32, 256 thr, warp tile 32x64. K % 32 == 0, K >= 128.
// OT: float or __half output. MODE: 0 plain, 1 fused column-sum (aux = zsum base,
// pre-offset per branch), 2 fused GroupNorm partials (aux = gnp).
#define HST 40
#define STG 4

template<typename OT, int MODE>
__global__ __launch_bounds__(256, 2)
void hgemm(const __half* __restrict__ A, int lda,
           const __half* __restrict__ Wt,
           const float* __restrict__ bias,
           OT* __restrict__ C, int ldc, int K,
           float* __restrict__ aux)
{
    extern __shared__ __half sh[];
    const uint32_t sbase = smem_u32(sh);
    const uint32_t BOFF  = STG * 128 * HST;

    const int tid  = threadIdx.x;
    const int wid  = tid >> 5;
    const int lane = tid & 31;
    const int warp_m = (wid & 3) * 32;
    const int warp_n = (wid >> 2) * 64;
    const long long rowTile = (long long)blockIdx.y * 128;
    const int colTile = blockIdx.x * 128;

    const int pr = tid >> 1;
    const int pc = (tid & 1) * 2;
    const __half* Abase = A + (rowTile + pr) * lda;
    const __half* Bbase = Wt + (long long)(colTile + pr) * K;
    const uint32_t aDst0 = sbase + (uint32_t)(pr * HST) * 2;
    const uint32_t bDst0 = sbase + (uint32_t)(BOFF + pr * HST) * 2;

    const int nk = K >> 5;

    float acc[2][8][4];
    #pragma unroll
    for (int mt = 0; mt < 2; mt++)
        #pragma unroll
        for (int nt = 0; nt < 8; nt++)
            #pragma unroll
            for (int i = 0; i < 4; i++) acc[mt][nt][i] = 0.f;

    auto issue = [&](int kt) {
        const int s = kt & (STG - 1);
        const uint32_t so = (uint32_t)(s * 128 * HST) * 2;
        const __half* ag = Abase + (kt << 5);
        const __half* bg = Bbase + (kt << 5);
        CP_ASYNC16(aDst0 + so + (pc    ) * 16, ag + (pc    ) * 8);
        CP_ASYNC16(aDst0 + so + (pc + 1) * 16, ag + (pc + 1) * 8);
        CP_ASYNC16(bDst0 + so + (pc    ) * 16, bg + (pc    ) * 8);
        CP_ASYNC16(bDst0 + so + (pc + 1) * 16, bg + (pc + 1) * 8);
        CP_COMMIT();
    };

    issue(0); issue(1); issue(2);

    const int a_r = lane & 15, a_h = lane >> 4;
    const int b_r = lane & 7, b_k = (lane >> 3) & 1, b_n = (lane >> 4) & 1;

    for (int kt = 0; kt < nk; kt++) {
        CP_WAIT2();
        __syncthreads();
        if (kt + 3 < nk) issue(kt + 3); else CP_COMMIT();

        const int s = kt & (STG - 1);
        const uint32_t aS = sbase + (uint32_t)((s * 128 + warp_m) * HST) * 2;
        const uint32_t bS = sbase + (uint32_t)(BOFF + (s * 128 + warp_n) * HST) * 2;

        #pragma unroll
        for (int ks = 0; ks < 2; ks++) {
            uint32_t af[2][4], bf[8][2];
            #pragma unroll
            for (int mt = 0; mt < 2; mt++)
                ldsm_x4(af[mt][0], af[mt][1], af[mt][2], af[mt][3],
                        aS + (uint32_t)((mt * 16 + a_r) * HST + ks * 16 + a_h * 8) * 2);
            #pragma unroll
            for (int p = 0; p < 4; p++)
                ldsm_x4(bf[2 * p][0], bf[2 * p][1], bf[2 * p + 1][0], bf[2 * p + 1][1],
                        bS + (uint32_t)((p * 16 + b_n * 8 + b_r) * HST + ks * 16 + b_k * 8) * 2);
            #pragma unroll
            for (int mt = 0; mt < 2; mt++)
                #pragma unroll
                for (int nt = 0; nt < 8; nt++)
                    mma_f16(acc[mt][nt], af[mt], bf[nt]);
        }
    }

    // ---------------- epilogue ----------------
    const int g = lane >> 2, tig = lane & 3;
    const int bidx = (int)(rowTile >> TSEQ_SHIFT);

    float cs[8][2];
    float gs = 0.f, gs2 = 0.f;
    if (MODE == 1) {
        #pragma unroll
        for (int nt = 0; nt < 8; nt++) { cs[nt][0] = 0.f; cs[nt][1] = 0.f; }
    }

    #pragma unroll
    for (int mt = 0; mt < 2; mt++) {
        long long r0 = rowTile + warp_m + mt * 16 + g;
        #pragma unroll
        for (int nt = 0; nt < 8; nt++) {
            int c0 = colTile + warp_n + nt * 8 + tig * 2;
            float b0 = __ldg(bias + c0), b1 = __ldg(bias + c0 + 1);
            float v0 = acc[mt][nt][0] + b0, v1 = acc[mt][nt][1] + b1;
            float v2 = acc[mt][nt][2] + b0, v3 = acc[mt][nt][3] + b1;
            if (sizeof(OT) == 2) {
                *(__half2*)((__half*)C + r0 * ldc + c0)       = __floats2half2_rn(v0, v1);
                *(__half2*)((__half*)C + (r0 + 8) * ldc + c0) = __floats2half2_rn(v2, v3);
            } else {
                *(float2*)((float*)C + r0 * ldc + c0)       = make_float2(v0, v1);
                *(float2*)((float*)C + (r0 + 8) * ldc + c0) = make_float2(v2, v3);
            }
            if (MODE == 1) { cs[nt][0] += v0 + v2; cs[nt][1] += v1 + v3; }
            if (MODE == 2) { gs += v0 + v1 + v2 + v3; gs2 += v0*v0 + v1*v1 + v2*v2 + v3*v3; }
        }
    }

    if (MODE == 1) {
        #pragma unroll
        for (int nt = 0; nt < 8; nt++) {
            float s0 = cs[nt][0], s1 = cs[nt][1];
            #pragma unroll
            for (int o = 4; o < 32; o <<= 1) {
                s0 += __shfl_xor_sync(0xffffffffu, s0, o);
                s1 += __shfl_xor_sync(0xffffffffu, s1, o);
            }
            if (lane < 4) {
                int c0 = colTile + warp_n + nt * 8 + tig * 2;
                atomicAdd(&aux[bidx * 640 + c0], s0);
                atomicAdd(&aux[bidx * 640 + c0 + 1], s1);
            }
        }
    }
    if (MODE == 2) {
        #pragma unroll
        for (int o = 16; o > 0; o >>= 1) {
            gs  += __shfl_xor_sync(0xffffffffu, gs, o);
            gs2 += __shfl_xor_sync(0xffffffffu, gs2, o);
        }
        if (lane == 0) {
            int grp = (colTile + warp_n) >> 6;
            atomicAdd(&aux[(bidx * 8 + grp) * 2], gs);
            atomicAdd(&aux[(bidx * 8 + grp) * 2 + 1], gs2);
        }
    }
}

// ---------------- zero accumulators ----------------
__global__ void zero_kernel(float* __restrict__ zs, float* __restrict__ gnp)
{
    int i = blockIdx.x * 256 + threadIdx.x;
    if (i < 64 * 640) zs[i] = 0.f;
    if (i < 64 * 8 * 2) gnp[i] = 0.f;
}

// ---------------- weight transpose + fp16 convert ----------------
__global__ __launch_bounds__(256)
void transpose_k(const float* __restrict__ W, int K, int N, __half* __restrict__ Wt)
{
    __shared__ float t[32][33];
    int kb = blockIdx.y * 32, nb = blockIdx.x * 32;
    int tx = threadIdx.x & 31, ty = threadIdx.x >> 5;
    #pragma unroll
    for (int i = 0; i < 4; i++)
        t[ty + i * 8][tx] = W[(long long)(kb + ty + i * 8) * N + nb + tx];
    __syncthreads();
    #pragma unroll
    for (int i = 0; i < 4; i++)
        Wt[(long long)(nb + ty + i * 8) * K + kb + tx] = __float2half_rn(t[tx][ty + i * 8]);
}

__global__ void biascat_kernel(const float* __restrict__ a, const float* __restrict__ b,
                               float* __restrict__ o)
{
    int i = blockIdx.x * 256 + threadIdx.x;
    if (i < 640) o[i] = a[i];
    else if (i < 1280) o[i] = b[i - 640];
}

// ---------------- fp32 SGEMM (stage-1, tiny K), fused SiLU, fp16 out ----------------
#define BM 128
#define BN_F 128
#define BK 16
__device__ __forceinline__ float2 ffma2(float2 a, float2 b, float2 c) {
    float2 d;
    asm("fma.rn.f32x2 %0, %1, %2, %3;"
        : "=l"(*(unsigned long long*)&d)
        : "l"(*(unsigned long long*)&a), "l"(*(unsigned long long*)&b), "l"(*(unsigned long long*)&c));
    return d;
}
__global__ __launch_bounds__(256, 2)
void sgemm_h(const float* __restrict__ A, int lda,
             const float* __restrict__ W, int ldw,
             const float* __restrict__ bias,
             __half* __restrict__ C, int ldc, int K)
{
    __shared__ float As[BK][BM + 1];
    __shared__ float Bs[BK][BN_F];
    const int tid = threadIdx.x;
    const int tx = tid & 15, ty = tid >> 4;
    const long long rowTile = (long long)blockIdx.y * BM;
    const int colTile = blockIdx.x * BN_F;
    float2 acc[8][4];
    #pragma unroll
    for (int i = 0; i < 8; i++)
        #pragma unroll
        for (int j = 0; j < 4; j++) acc[i][j] = make_float2(0.f, 0.f);
    for (int k0 = 0; k0 < K; k0 += BK) {
        #pragma unroll
        for (int i = 0; i < 8; i++) {
            int idx = tid + i * 256;
            int m = idx >> 4, kk = idx & 15;
            int kg = k0 + kk;
            As[kk][m] = (kg < K) ? A[(rowTile + m) * lda + kg] : 0.f;
        }
        #pragma unroll
        for (int i = 0; i < 8; i++) {
            int idx = tid + i * 256;
            int kk = idx >> 7, n = idx & 127;
            int kg = k0 + kk;
            Bs[kk][n] = (kg < K) ? W[(long long)kg * ldw + colTile + n] : 0.f;
        }
        __syncthreads();
        #pragma unroll
        for (int kk = 0; kk < BK; kk++) {
            float2 b[4]; float a[8];
            #pragma unroll
            for (int j = 0; j < 4; j++) b[j] = *(const float2*)&Bs[kk][tx * 2 + j * 32];
            #pragma unroll
            for (int i = 0; i < 8; i++) a[i] = As[kk][ty * 8 + i];
            #pragma unroll
            for (int i = 0; i < 8; i++) {
                float2 a2 = make_float2(a[i], a[i]);
                #pragma unroll
                for (int j = 0; j < 4; j++) acc[i][j] = ffma2(a2, b[j], acc[i][j]);
            }
        }
        __syncthreads();
    }
    #pragma unroll
    for (int i = 0; i < 8; i++) {
        long long row = rowTile + ty * 8 + i;
        #pragma unroll
        for (int j = 0; j < 4; j++) {
            int col = colTile + tx * 2 + j * 32;
            float vx = acc[i][j].x + bias[col];
            float vy = acc[i][j].y + bias[col + 1];
            vx = vx * sigmoid_f(vx);
            vy = vy * sigmoid_f(vy);
            *(__half2*)&C[row * ldc + col] = __floats2half2_rn(vx, vy);
        }
    }
}

// ---------------- SE block ----------------
__global__ __launch_bounds__(256)
void se_kernel(const float* __restrict__ zsum, const float* __restrict__ w1,
               const float* __restrict__ w2, float* __restrict__ se)
{
    int b = blockIdx.x;
    __shared__ float avg[640];
    __shared__ float r[160];
    for (int c = threadIdx.x; c < 640; c += 256)
        avg[c] = zsum[b * 640 + c] * (1.f / 2048.f);
    __syncthreads();
    for (int j = threadIdx.x; j < 160; j += 256) {
        float s = 0.f;
        for (int k = 0; k < 640; k++) s += avg[k] * w1[k * 160 + j];
        r[j] = fmaxf(s, 0.f);
    }
    __syncthreads();
    for (int j = threadIdx.x; j < 640; j += 256) {
        float s = 0.f;
        for (int k = 0; k < 160; k++) s += r[k] * w2[k * 640 + j];
        se[b * 640 + j] = sigmoid_f(s);
    }
}

// z_se = z(fp16) * se[batch] -> fp16
__global__ __launch_bounds__(256)
void zse_kernel(const __half* __restrict__ zh, const float* __restrict__ se,
                __half* __restrict__ out)
{
    const long long total = (long long)NTOK * 160;   // 4-half groups
    for (long long i = (long long)blockIdx.x * blockDim.x + threadIdx.x;
         i < total; i += (long long)gridDim.x * blockDim.x) {
        long long row = i / 160;
        int q = (int)(i - row * 160);
        int b = (int)(row >> TSEQ_SHIFT);
        uint2 zp = *(const uint2*)&zh[row * 640 + q * 4];
        float4 sv = *(const float4*)&se[b * 640 + q * 4];
        float2 z0 = __half22float2(*(__half2*)&zp.x);
        float2 z1 = __half22float2(*(__half2*)&zp.y);
        __half2 h0 = __floats2half2_rn(z0.x * sv.x, z0.y * sv.y);
        __half2 h1 = __floats2half2_rn(z1.x * sv.z, z1.y * sv.w);
        *(uint2*)&out[row * 640 + q * 4] = make_uint2(*(uint32_t*)&h0, *(uint32_t*)&h1);
    }
}

// ---------------- gate + LayerNorm (fp16 inputs) ----------------
__global__ __launch_bounds__(320)
void gate_ln_kernel(const __half* __restrict__ zse, const __half* __restrict__ y,
                    const float* __restrict__ lnw, const float* __restrict__ lnb,
                    __half* __restrict__ hout)
{
    long long row = blockIdx.x;
    const __half* zr = zse + row * 640;
    const __half* yr = y + row * 1280;
    __shared__ float hs[640];
    __shared__ float wsum[10], wsum2[10], stats[2];
    float s = 0.f, s2 = 0.f;
    #pragma unroll
    for (int u = 0; u < 2; u++) {
        int c = threadIdx.x + u * 320;
        float zv = __half2float(zr[c]);
        float gv = sigmoid_f(__half2float(yr[c]));
        float pv = __half2float(yr[640 + c]);
        float h = gv * pv + (1.f - gv) * zv;
        hs[c] = h; s += h; s2 += h * h;
    }
    s = warp_sum(s); s2 = warp_sum(s2);
    int lane = threadIdx.x & 31, wid = threadIdx.x >> 5;
    if (lane == 0) { wsum[wid] = s; wsum2[wid] = s2; }
    __syncthreads();
    if (threadIdx.x == 0) {
        float a = 0.f, b2 = 0.f;
        #pragma unroll
        for (int i = 0; i < 10; i++) { a += wsum[i]; b2 += wsum2[i]; }
        float mu  = a * (1.f / 640.f);
        float var = b2 * (1.f / 640.f) - mu * mu;
        stats[0] = mu; stats[1] = rsqrtf(var + 1e-5f);
    }
    __syncthreads();
    float mu = stats[0], rs = stats[1];
    #pragma unroll
    for (int u = 0; u < 2; u++) {
        int c = threadIdx.x + u * 320;
        hout[row * 640 + c] = __float2half_rn((hs[c] - mu) * rs * lnw[c] + lnb[c]);
    }
}

// ---------------- GroupNorm finalize + apply ----------------
__global__ void gnfinal_kernel(const float* __restrict__ gnp, float* __restrict__ gst)
{
    int i = blockIdx.x * 256 + threadIdx.x;
    if (i < 512) {
        double mean = (double)gnp[i * 2] / 131072.0;
        double var  = (double)gnp[i * 2 + 1] / 131072.0 - mean * mean;
        gst[i * 2 + 0] = (float)mean;
        gst[i * 2 + 1] = (float)rsqrt(var + 1e-5);
    }
}

__global__ __launch_bounds__(256)
void gnapply_kernel(const float* __restrict__ out, const float* __restrict__ gst,
                    const float* __restrict__ gw, const float* __restrict__ gb,
                    float* __restrict__ dst)
{
    const long long total = (long long)NTOK * 128;
    for (long long i = (long long)blockIdx.x * blockDim.x + threadIdx.x;
         i < total; i += (long long)gridDim.x * blockDim.x) {
        long long row = i >> 7;
        int q = (int)(i & 127);
        int d = q * 4;
        int b = (int)(row >> TSEQ_SHIFT);
        int g = d >> 6;
        float mean = gst[(b * 8 + g) * 2 + 0];
        float rs   = gst[(b * 8 + g) * 2 + 1];
        float4 v  = *(const float4*)&out[(row << 9) + d];
        float4 w  = *(const float4*)&gw[d];
        float4 bb = *(const float4*)&gb[d];
        float4 r;
        r.x = (v.x - mean) * rs * w.x + bb.x;
        r.y = (v.y - mean) * rs * w.y + bb.y;
        r.z = (v.z - mean) * rs * w.z + bb.z;
        r.w = (v.w - mean) * rs * w.w + bb.w;
        *(float4*)&dst[(row << 9) + d] = r;
    }
}

// ---------------- launch ----------------
extern "C" void kernel_launch(void* const* d_in, const int* in_sizes, int n_in,
                              void* d_out, int out_size)
{
    const float* x    = (const float*)d_in[0];
    const float* hw1  = (const float*)d_in[1];
    const float* hb1  = (const float*)d_in[2];
    const float* hw2  = (const float*)d_in[3];
    const float* hb2  = (const float*)d_in[4];
    const float* lw1  = (const float*)d_in[5];
    const float* lb1  = (const float*)d_in[6];
    const float* lw2  = (const float*)d_in[7];
    const float* lb2  = (const float*)d_in[8];
    const float* ew1  = (const float*)d_in[9];
    const float* eb1  = (const float*)d_in[10];
    const float* ew2  = (const float*)d_in[11];
    const float* eb2  = (const float*)d_in[12];
    const float* sew1 = (const float*)d_in[13];
    const float* sew2 = (const float*)d_in[14];
    const float* gwv  = (const float*)d_in[15];
    const float* gbv  = (const float*)d_in[16];
    const float* pwv  = (const float*)d_in[17];
    const float* pbv  = (const float*)d_in[18];
    const float* lnw  = (const float*)d_in[19];
    const float* lnb  = (const float*)d_in[20];
    const float* owv  = (const float*)d_in[21];
    const float* obv  = (const float*)d_in[22];
    const float* gnw  = (const float*)d_in[23];
    const float* gnb  = (const float*)d_in[24];
    float* dst = (float*)d_out;

    __half *a1h, *zh, *zseh, *yh, *hh, *wty, *wto, *wth, *wtl, *wte;
    float *ob, *zs, *se, *gnp, *gn, *by;
    cudaGetSymbolAddress((void**)&a1h,  g_a1h);
    cudaGetSymbolAddress((void**)&zh,   g_zh);
    cudaGetSymbolAddress((void**)&zseh, g_zseh);
    cudaGetSymbolAddress((void**)&yh,   g_yh);
    cudaGetSymbolAddress((void**)&hh,   g_hh);
    cudaGetSymbolAddress((void**)&ob, g_o);
    cudaGetSymbolAddress((void**)&zs, g_zsum);
    cudaGetSymbolAddress((void**)&se, g_se);
    cudaGetSymbolAddress((void**)&gnp, g_gnp);
    cudaGetSymbolAddress((void**)&gn,  g_gn);
    cudaGetSymbolAddress((void**)&wty, g_wty);
    cudaGetSymbolAddress((void**)&wto, g_wto);
    cudaGetSymbolAddress((void**)&wth, g_wth);
    cudaGetSymbolAddress((void**)&wtl, g_wtl);
    cudaGetSymbolAddress((void**)&wte, g_wte);
    cudaGetSymbolAddress((void**)&by,  g_by);

    const int HSMEM = STG * 128 * HST * 2 * 2;   // 81920 bytes
    cudaFuncSetAttribute((hgemm<__half, 1>), cudaFuncAttributeMaxDynamicSharedMemorySize, HSMEM);
    cudaFuncSetAttribute((hgemm<__half, 0>), cudaFuncAttributeMaxDynamicSharedMemorySize, HSMEM);
    cudaFuncSetAttribute((hgemm<float, 2>),  cudaFuncAttributeMaxDynamicSharedMemorySize, HSMEM);

    zero_kernel<<<160, 256>>>(zs, gnp);

    transpose_k<<<dim3(640 / 32, 640 / 32), 256>>>(gwv, 640, 640, wty);
    transpose_k<<<dim3(640 / 32, 640 / 32), 256>>>(pwv, 640, 640, wty + 640 * 640);
    transpose_k<<<dim3(512 / 32, 640 / 32), 256>>>(owv, 640, 512, wto);
    transpose_k<<<dim3(256 / 32, 256 / 32), 256>>>(hw2, 256, 256, wth);
    transpose_k<<<dim3(256 / 32, 256 / 32), 256>>>(lw2, 256, 256, wtl);
    transpose_k<<<dim3(128 / 32, 128 / 32), 256>>>(ew2, 128, 128, wte);
    biascat_kernel<<<5, 256>>>(gbv, pbv, by);

    const dim3 blk(256);
    const int MY = NTOK / 128;

    // stage 1 (fp32 FFMA, tiny K) -> fp16 a1
    sgemm_h<<<dim3(2, MY), blk>>>(x +  0, 44, hw1, 256, hb1, a1h +   0, 640, 14);
    sgemm_h<<<dim3(2, MY), blk>>>(x + 14, 44, lw1, 256, lb1, a1h + 256, 640, 22);
    sgemm_h<<<dim3(1, MY), blk>>>(x + 36, 44, ew1, 128, eb1, a1h + 512, 640,  8);

    // stage 2 (HMMA): z(fp16) = a1_branch @ w2 + b2, fused SE column sums
    hgemm<__half, 1><<<dim3(2, MY), blk, HSMEM>>>(a1h +   0, 640, wth, hb2, zh +   0, 640, 256, zs +   0);
    hgemm<__half, 1><<<dim3(2, MY), blk, HSMEM>>>(a1h + 256, 640, wtl, lb2, zh + 256, 640, 256, zs + 256);
    hgemm<__half, 1><<<dim3(1, MY), blk, HSMEM>>>(a1h + 512, 640, wte, eb2, zh + 512, 640, 128, zs + 512);

    // SE path
    se_kernel<<<64, 256>>>(zs, sew1, sew2, se);
    zse_kernel<<<2048, 256>>>(zh, se, zseh);

    // stage 3 (HMMA): y(fp16) = z_se @ [gw|pw] + [gb|pb]
    hgemm<__half, 0><<<dim3(10, MY), blk, HSMEM>>>(zseh, 640, wty, by, yh, 1280, 640, nullptr);

    // gate + LayerNorm -> fp16 h
    gate_ln_kernel<<<NTOK, 320>>>(zseh, yh, lnw, lnb, hh);

    // output projection (HMMA), fused GroupNorm partials
    hgemm<float, 2><<<dim3(4, MY), blk, HSMEM>>>(hh, 640, wto, obv, ob, 512, 640, gnp);

    // GroupNorm finalize + apply
    gnfinal_kernel<<<2, 256>>>(gnp, gn);
    gnapply_kernel<<<2048, 256>>>(ob, gn, gnw, gnb, dst);
}